// round 2
// baseline (speedup 1.0000x reference)
#include <cuda_runtime.h>

#define CDIM 64
#define MAXN 100000

typedef unsigned long long u64;

__device__ float g_q[MAXN * CDIM];
__device__ float g_k[MAXN * CDIM];
__device__ float g_v[MAXN * CDIM];
__device__ float g_acc[MAXN * CDIM * 2];   // [node][chan][{num, denom}]

__device__ __forceinline__ void red_add_v4(float* p, float a, float b, float c, float d) {
    asm volatile("red.global.add.v4.f32 [%0], {%1, %2, %3, %4};"
                 :: "l"(p), "f"(a), "f"(b), "f"(c), "f"(d) : "memory");
}
__device__ __forceinline__ void fma2(u64& d, u64 a, u64 b) {
    asm("fma.rn.f32x2 %0, %1, %2, %0;" : "+l"(d) : "l"(a), "l"(b));
}
__device__ __forceinline__ u64 pack2(float x, float y) {
    u64 r; asm("mov.b64 %0, {%1, %2};" : "=l"(r) : "f"(x), "f"(y)); return r;
}
__device__ __forceinline__ float2 unpack2(u64 v) {
    float lo, hi; asm("mov.b64 {%0, %1}, %2;" : "=f"(lo), "=f"(hi) : "l"(v));
    return make_float2(lo, hi);
}

// ---------------------------------------------------------------------------
__global__ void k_zero(int n4) {
    int i = blockIdx.x * blockDim.x + threadIdx.x;
    if (i < n4) ((float4*)g_acc)[i] = make_float4(0.f, 0.f, 0.f, 0.f);
}

// ---------------------------------------------------------------------------
// Node: h = LN(relu(x@W_in+b)); q=h@W_dst; k=h@W_src; v=h@W_lin
// warp-per-node, lane owns channels {2l,2l+1}; activations duplicated in smem
// so packed fma.rn.f32x2 consumes them directly.
// ---------------------------------------------------------------------------
__global__ void __launch_bounds__(256) k_node(
        int N, const float* __restrict__ x,
        const float* __restrict__ W_in, const float* __restrict__ b_in,
        const float* __restrict__ ln_g, const float* __restrict__ ln_b,
        const float* __restrict__ W_lin, const float* __restrict__ W_src,
        const float* __restrict__ W_dst) {
    extern __shared__ float sm[];
    float* sWin = sm;
    float* sWq  = sm + 4096;
    float* sWk  = sm + 8192;
    float* sWv  = sm + 12288;
    float* sP   = sm + 16384;          // b_in, ln_g, ln_b
    float* sScr = sm + 16576;          // 8 warps * 128 floats (64 dup pairs)

    for (int i = threadIdx.x; i < 4096; i += blockDim.x) {
        sWin[i] = W_in[i]; sWq[i] = W_dst[i]; sWk[i] = W_src[i]; sWv[i] = W_lin[i];
    }
    if (threadIdx.x < 64) {
        sP[threadIdx.x]       = b_in[threadIdx.x];
        sP[64 + threadIdx.x]  = ln_g[threadIdx.x];
        sP[128 + threadIdx.x] = ln_b[threadIdx.x];
    }
    __syncthreads();

    const int warp = threadIdx.x >> 5, lane = threadIdx.x & 31;
    const int c0 = lane * 2;
    float* dupf = sScr + warp * 128;
    const ulonglong2* dup2 = (const ulonglong2*)dupf;
    const int gw = blockIdx.x * 8 + warp;
    const int nw = gridDim.x * 8;
    const u64* wIn = (const u64*)sWin;
    const u64* wQ  = (const u64*)sWq;
    const u64* wK  = (const u64*)sWk;
    const u64* wV  = (const u64*)sWv;

    for (int n = gw; n < N; n += nw) {
        float2 xv = *(const float2*)(x + (size_t)n * 64 + c0);
        *(float4*)(dupf + c0 * 2) = make_float4(xv.x, xv.x, xv.y, xv.y);
        __syncwarp();

        u64 acc = pack2(sP[c0], sP[c0 + 1]);
        #pragma unroll 8
        for (int hh = 0; hh < 32; hh++) {
            ulonglong2 a = dup2[hh];
            fma2(acc, a.x, wIn[(2 * hh) * 32 + lane]);
            fma2(acc, a.y, wIn[(2 * hh + 1) * 32 + lane]);
        }
        float2 t = unpack2(acc);
        float ta = fmaxf(t.x, 0.f), tb = fmaxf(t.y, 0.f);

        float s1 = ta + tb, s2 = ta * ta + tb * tb;
        #pragma unroll
        for (int o = 16; o > 0; o >>= 1) {
            s1 += __shfl_xor_sync(0xffffffffu, s1, o);
            s2 += __shfl_xor_sync(0xffffffffu, s2, o);
        }
        float mu  = s1 * 0.015625f;
        float var = s2 * 0.015625f - mu * mu;
        float inv = rsqrtf(var + 1e-5f);
        float ha = (ta - mu) * inv * sP[64 + c0]     + sP[128 + c0];
        float hb = (tb - mu) * inv * sP[64 + c0 + 1] + sP[128 + c0 + 1];
        __syncwarp();   // all lanes done reading x-dup
        *(float4*)(dupf + c0 * 2) = make_float4(ha, ha, hb, hb);
        __syncwarp();

        u64 aq = pack2(0.f, 0.f), ak = aq, av = aq;
        #pragma unroll 8
        for (int hh = 0; hh < 32; hh++) {
            ulonglong2 a = dup2[hh];
            u64 q0 = wQ[(2 * hh) * 32 + lane], q1 = wQ[(2 * hh + 1) * 32 + lane];
            u64 k0 = wK[(2 * hh) * 32 + lane], k1 = wK[(2 * hh + 1) * 32 + lane];
            u64 v0 = wV[(2 * hh) * 32 + lane], v1 = wV[(2 * hh + 1) * 32 + lane];
            fma2(aq, a.x, q0); fma2(aq, a.y, q1);
            fma2(ak, a.x, k0); fma2(ak, a.y, k1);
            fma2(av, a.x, v0); fma2(av, a.y, v1);
        }
        *(float2*)(g_q + (size_t)n * 64 + c0) = unpack2(aq);
        *(float2*)(g_k + (size_t)n * 64 + c0) = unpack2(ak);
        *(float2*)(g_v + (size_t)n * 64 + c0) = unpack2(av);
        __syncwarp();
    }
}

// ---------------------------------------------------------------------------
// Edge kernel: 4 edges per warp, packed fma.rn.f32x2, single pass softmax.
// ---------------------------------------------------------------------------
__device__ __forceinline__ void mlp4(const u64* __restrict__ W,
                                     const ulonglong2* __restrict__ dup2,
                                     u64 bias, u64 acc[4], int lane) {
    acc[0] = bias; acc[1] = bias; acc[2] = bias; acc[3] = bias;
    #pragma unroll 8
    for (int hh = 0; hh < 32; hh++) {
        u64 w0 = W[(2 * hh) * 32 + lane];
        u64 w1 = W[(2 * hh + 1) * 32 + lane];
        ulonglong2 a0 = dup2[hh];
        ulonglong2 a1 = dup2[32 + hh];
        ulonglong2 a2 = dup2[64 + hh];
        ulonglong2 a3 = dup2[96 + hh];
        fma2(acc[0], a0.x, w0); fma2(acc[0], a0.y, w1);
        fma2(acc[1], a1.x, w0); fma2(acc[1], a1.y, w1);
        fma2(acc[2], a2.x, w0); fma2(acc[2], a2.y, w1);
        fma2(acc[3], a3.x, w0); fma2(acc[3], a3.y, w1);
    }
}

__global__ void __launch_bounds__(256) k_edge(
        int E, const int* __restrict__ ei, const float* __restrict__ pos,
        const float* __restrict__ pnW1, const float* __restrict__ pnb1,
        const float* __restrict__ pnW2, const float* __restrict__ pnb2,
        const float* __restrict__ anW1, const float* __restrict__ anb1,
        const float* __restrict__ anW2, const float* __restrict__ anb2) {
    extern __shared__ float sm[];
    float* sPnW1 = sm;                   // 192
    float* sPnW2 = sm + 192;             // 4096
    float* sAnW1 = sm + 4288;            // 4096
    float* sAnW2 = sm + 8384;            // 4096
    float* sBias = sm + 12480;           // 256
    float* sDup  = sm + 12736;           // 8 warps * 512 floats

    for (int i = threadIdx.x; i < 192; i += blockDim.x) sPnW1[i] = pnW1[i];
    for (int i = threadIdx.x; i < 4096; i += blockDim.x) {
        sPnW2[i] = pnW2[i]; sAnW1[i] = anW1[i]; sAnW2[i] = anW2[i];
    }
    if (threadIdx.x < 64) {
        sBias[threadIdx.x]       = pnb1[threadIdx.x];
        sBias[64 + threadIdx.x]  = pnb2[threadIdx.x];
        sBias[128 + threadIdx.x] = anb1[threadIdx.x];
        sBias[192 + threadIdx.x] = anb2[threadIdx.x];
    }
    __syncthreads();

    const int warp = threadIdx.x >> 5, lane = threadIdx.x & 31;
    const int c0 = lane * 2;
    float* dupf = sDup + warp * 512;     // [edge][64 h] duplicated float2
    const ulonglong2* dup2 = (const ulonglong2*)dupf;
    const int gw = blockIdx.x * 8 + warp;
    const int nw = gridDim.x * 8;
    const float2* W1p = (const float2*)sPnW1;
    const u64* W2p = (const u64*)sPnW2;
    const u64* W1a = (const u64*)sAnW1;
    const u64* W2a = (const u64*)sAnW2;

    const u64 biasP2 = pack2(sBias[64 + c0],  sBias[64 + c0 + 1]);
    const u64 biasA1 = pack2(sBias[128 + c0], sBias[128 + c0 + 1]);
    const u64 biasA2 = pack2(sBias[192 + c0], sBias[192 + c0 + 1]);
    const float b1a = sBias[c0], b1b = sBias[c0 + 1];
    const float2 w0 = W1p[lane], w1 = W1p[32 + lane], w2 = W1p[64 + lane];

    u64 acc[4];
    float2 dl[4];

    for (int e0 = gw * 4; e0 < E; e0 += nw * 4) {
        int s[4], d[4];
        #pragma unroll
        for (int e = 0; e < 4; e++) {
            int idx = (e0 + e < E) ? e0 + e : e0;
            s[e] = ei[idx];
            d[e] = ei[E + idx];
        }

        // pos MLP layer 1 (3 -> 64), write duplicated relu to smem
        #pragma unroll
        for (int e = 0; e < 4; e++) {
            float px = pos[d[e] * 3 + 0] - pos[s[e] * 3 + 0];
            float py = pos[d[e] * 3 + 1] - pos[s[e] * 3 + 1];
            float pz = pos[d[e] * 3 + 2] - pos[s[e] * 3 + 2];
            float ha = fmaf(pz, w2.x, fmaf(py, w1.x, fmaf(px, w0.x, b1a)));
            float hb = fmaf(pz, w2.y, fmaf(py, w1.y, fmaf(px, w0.y, b1b)));
            ha = fmaxf(ha, 0.f); hb = fmaxf(hb, 0.f);
            *(float4*)(dupf + e * 128 + c0 * 2) = make_float4(ha, ha, hb, hb);
        }
        __syncwarp();

        // pos MLP layer 2 (64 -> 64) -> delta (relu, kept in regs)
        mlp4(W2p, dup2, biasP2, acc, lane);
        #pragma unroll
        for (int e = 0; e < 4; e++) {
            float2 t = unpack2(acc[e]);
            dl[e] = make_float2(fmaxf(t.x, 0.f), fmaxf(t.y, 0.f));
        }
        __syncwarp();   // done reading pos-h dup

        // attn input: q[d] - k[s] + delta -> duplicated smem
        #pragma unroll
        for (int e = 0; e < 4; e++) {
            float2 qv = *(const float2*)(g_q + (size_t)d[e] * 64 + c0);
            float2 kv = *(const float2*)(g_k + (size_t)s[e] * 64 + c0);
            float ba = qv.x - kv.x + dl[e].x;
            float bb = qv.y - kv.y + dl[e].y;
            *(float4*)(dupf + e * 128 + c0 * 2) = make_float4(ba, ba, bb, bb);
        }
        __syncwarp();

        // attn MLP layer 1 (64 -> 64) -> relu -> duplicated smem
        mlp4(W1a, dup2, biasA1, acc, lane);
        __syncwarp();   // done reading B dup
        #pragma unroll
        for (int e = 0; e < 4; e++) {
            float2 t = unpack2(acc[e]);
            float ga = fmaxf(t.x, 0.f), gb = fmaxf(t.y, 0.f);
            *(float4*)(dupf + e * 128 + c0 * 2) = make_float4(ga, ga, gb, gb);
        }
        __syncwarp();

        // attn MLP layer 2 (64 -> 64) -> alpha -> relu -> exp -> RED
        mlp4(W2a, dup2, biasA2, acc, lane);
        #pragma unroll
        for (int e = 0; e < 4; e++) {
            if (e0 + e < E) {
                float2 t = unpack2(acc[e]);
                float exa = __expf(fmaxf(t.x, 0.f));
                float exb = __expf(fmaxf(t.y, 0.f));
                float2 vv = *(const float2*)(g_v + (size_t)s[e] * 64 + c0);
                red_add_v4(g_acc + (size_t)d[e] * 128 + lane * 4,
                           exa * (vv.x + dl[e].x), exa,
                           exb * (vv.y + dl[e].y), exb);
            }
        }
        __syncwarp();   // done reading dup before next iteration overwrites
    }
}

// ---------------------------------------------------------------------------
// Output: out = relu((num / (den + 1e-16)) @ W_out + b_out)
// ---------------------------------------------------------------------------
__global__ void __launch_bounds__(256) k_out(
        int N, const float* __restrict__ W_out, const float* __restrict__ b_out,
        float* __restrict__ out) {
    extern __shared__ float sm[];
    float* sW   = sm;           // 4096
    float* sb   = sm + 4096;    // 64
    float* sScr = sm + 4160;    // 8 warps * 128

    for (int i = threadIdx.x; i < 4096; i += blockDim.x) sW[i] = W_out[i];
    if (threadIdx.x < 64) sb[threadIdx.x] = b_out[threadIdx.x];
    __syncthreads();

    const int warp = threadIdx.x >> 5, lane = threadIdx.x & 31;
    const int c0 = lane * 2;
    float* dupf = sScr + warp * 128;
    const ulonglong2* dup2 = (const ulonglong2*)dupf;
    const int gw = blockIdx.x * 8 + warp;
    const int nw = gridDim.x * 8;
    const u64* wO = (const u64*)sW;

    for (int n = gw; n < N; n += nw) {
        float4 ld = *(const float4*)(g_acc + (size_t)n * 128 + lane * 4);
        float va = ld.x / (ld.y + 1e-16f);
        float vb = ld.z / (ld.w + 1e-16f);
        *(float4*)(dupf + c0 * 2) = make_float4(va, va, vb, vb);
        __syncwarp();
        u64 acc = pack2(sb[c0], sb[c0 + 1]);
        #pragma unroll 8
        for (int hh = 0; hh < 32; hh++) {
            ulonglong2 a = dup2[hh];
            fma2(acc, a.x, wO[(2 * hh) * 32 + lane]);
            fma2(acc, a.y, wO[(2 * hh + 1) * 32 + lane]);
        }
        float2 t = unpack2(acc);
        *(float2*)(out + (size_t)n * 64 + c0) =
            make_float2(fmaxf(t.x, 0.f), fmaxf(t.y, 0.f));
        __syncwarp();
    }
}

// ---------------------------------------------------------------------------

#define NODE_SMEM ((16576 + 8 * 128) * 4)   // 70400 B
#define EDGE_SMEM ((12736 + 8 * 512) * 4)   // 67328 B
#define OUT_SMEM  ((4160 + 8 * 128) * 4)    // 20736 B

extern "C" void kernel_launch(void* const* d_in, const int* in_sizes, int n_in,
                              void* d_out, int out_size) {
    const float* x     = (const float*)d_in[0];
    const float* pos   = (const float*)d_in[1];
    const int*   ei    = (const int*)d_in[2];
    const float* W_in  = (const float*)d_in[3];
    const float* b_in  = (const float*)d_in[4];
    const float* ln_g  = (const float*)d_in[5];
    const float* ln_b  = (const float*)d_in[6];
    const float* W_lin = (const float*)d_in[7];
    const float* W_src = (const float*)d_in[8];
    const float* W_dst = (const float*)d_in[9];
    const float* pnW1  = (const float*)d_in[10];
    const float* pnb1  = (const float*)d_in[11];
    const float* pnW2  = (const float*)d_in[12];
    const float* pnb2  = (const float*)d_in[13];
    const float* anW1  = (const float*)d_in[14];
    const float* anb1  = (const float*)d_in[15];
    const float* anW2  = (const float*)d_in[16];
    const float* anb2  = (const float*)d_in[17];
    const float* W_out = (const float*)d_in[18];
    const float* b_out = (const float*)d_in[19];

    const int N = in_sizes[0] / 64;
    const int E = in_sizes[2] / 2;

    cudaFuncSetAttribute(k_node, cudaFuncAttributeMaxDynamicSharedMemorySize, NODE_SMEM);
    cudaFuncSetAttribute(k_edge, cudaFuncAttributeMaxDynamicSharedMemorySize, EDGE_SMEM);

    const int n4 = N * 32;
    k_zero<<<(n4 + 255) / 256, 256>>>(n4);
    k_node<<<296, 256, NODE_SMEM>>>(N, x, W_in, b_in, ln_g, ln_b, W_lin, W_src, W_dst);
    k_edge<<<296, 256, EDGE_SMEM>>>(E, ei, pos, pnW1, pnb1, pnW2, pnb2,
                                    anW1, anb1, anW2, anb2);
    k_out<<<592, 256, OUT_SMEM>>>(N, W_out, b_out, (float*)d_out);
}

// round 3
// speedup vs baseline: 2.3230x; 2.3230x over previous
#include <cuda_runtime.h>
#include <cuda_bf16.h>

#define CDIM 64
#define MAXN 100000

__device__ float g_q[MAXN * CDIM];
__device__ float g_k[MAXN * CDIM];
__device__ float g_v[MAXN * CDIM];
__device__ float g_acc[MAXN * CDIM * 2];   // [node][chan][{num, denom}]

__device__ __forceinline__ void red_add_v4(float* p, float a, float b, float c, float d) {
    asm volatile("red.global.add.v4.f32 [%0], {%1, %2, %3, %4};"
                 :: "l"(p), "f"(a), "f"(b), "f"(c), "f"(d) : "memory");
}
// pack two f32 into bf16x2: low 16 bits = lo_val, high = hi_val
__device__ __forceinline__ unsigned pack_bf16x2(float lo_val, float hi_val) {
    unsigned r;
    asm("cvt.rn.bf16x2.f32 %0, %1, %2;" : "=r"(r) : "f"(hi_val), "f"(lo_val));
    return r;
}
__device__ __forceinline__ float bfx2_lo_f32(unsigned p) { return __uint_as_float(p << 16); }
__device__ __forceinline__ float bfx2_hi_f32(unsigned p) { return __uint_as_float(p & 0xFFFF0000u); }

// split (v0,v1) into hi/lo bf16x2 pairs: v ~= hi + lo with ~2^-17 residual
__device__ __forceinline__ void split_pair(float v0, float v1, unsigned& hi, unsigned& lo) {
    hi = pack_bf16x2(v0, v1);
    float r0 = v0 - bfx2_lo_f32(hi);
    float r1 = v1 - bfx2_hi_f32(hi);
    lo = pack_bf16x2(r0, r1);
}

__device__ __forceinline__ void mma_bf16(float d[4],
        unsigned a0, unsigned a1, unsigned a2, unsigned a3,
        unsigned b0, unsigned b1) {
    asm("mma.sync.aligned.m16n8k16.row.col.f32.bf16.bf16.f32 "
        "{%0,%1,%2,%3}, {%4,%5,%6,%7}, {%8,%9}, {%0,%1,%2,%3};"
        : "+f"(d[0]), "+f"(d[1]), "+f"(d[2]), "+f"(d[3])
        : "r"(a0), "r"(a1), "r"(a2), "r"(a3), "r"(b0), "r"(b1));
}

// ---------------------------------------------------------------------------
__global__ void k_zero(int n4) {
    int i = blockIdx.x * blockDim.x + threadIdx.x;
    if (i < n4) ((float4*)g_acc)[i] = make_float4(0.f, 0.f, 0.f, 0.f);
}

// ---------------------------------------------------------------------------
// Node preprocessing (round-1 variant): h = LN(relu(x@W_in+b)); q,k,v GEMVs.
// ---------------------------------------------------------------------------
__global__ void k_node(int N, const float* __restrict__ x,
                       const float* __restrict__ W_in, const float* __restrict__ b_in,
                       const float* __restrict__ ln_g, const float* __restrict__ ln_b,
                       const float* __restrict__ W_lin, const float* __restrict__ W_src,
                       const float* __restrict__ W_dst) {
    extern __shared__ float sm[];
    float* sWin = sm;
    float* sWq  = sm + 4096;
    float* sWk  = sm + 8192;
    float* sWv  = sm + 12288;
    float* sP   = sm + 16384;
    float* sScr = sm + 16384 + 192;

    for (int i = threadIdx.x; i < 4096; i += blockDim.x) {
        sWin[i] = W_in[i]; sWq[i] = W_dst[i]; sWk[i] = W_src[i]; sWv[i] = W_lin[i];
    }
    if (threadIdx.x < 64) {
        sP[threadIdx.x]       = b_in[threadIdx.x];
        sP[64 + threadIdx.x]  = ln_g[threadIdx.x];
        sP[128 + threadIdx.x] = ln_b[threadIdx.x];
    }
    __syncthreads();

    const int warp = threadIdx.x >> 5, lane = threadIdx.x & 31;
    const int c0 = lane * 2;
    float* A = sScr + warp * 128;
    float* B = A + 64;
    const int gw = blockIdx.x * (blockDim.x >> 5) + warp;
    const int nw = gridDim.x * (blockDim.x >> 5);
    const float2* wIn = (const float2*)sWin;
    const float2* wQ  = (const float2*)sWq;
    const float2* wK  = (const float2*)sWk;
    const float2* wV  = (const float2*)sWv;

    for (int n = gw; n < N; n += nw) {
        float2 xv = *(const float2*)(x + (size_t)n * 64 + c0);
        A[c0] = xv.x; A[c0 + 1] = xv.y;
        __syncwarp();

        float ta = sP[c0], tb = sP[c0 + 1];
        #pragma unroll 16
        for (int h = 0; h < 64; h++) {
            float2 w = wIn[h * 32 + lane];
            float hv = A[h];
            ta = fmaf(hv, w.x, ta); tb = fmaf(hv, w.y, tb);
        }
        ta = fmaxf(ta, 0.f); tb = fmaxf(tb, 0.f);

        float s1 = ta + tb, s2 = ta * ta + tb * tb;
        #pragma unroll
        for (int o = 16; o > 0; o >>= 1) {
            s1 += __shfl_xor_sync(0xffffffffu, s1, o);
            s2 += __shfl_xor_sync(0xffffffffu, s2, o);
        }
        float mu  = s1 * 0.015625f;
        float var = s2 * 0.015625f - mu * mu;
        float inv = rsqrtf(var + 1e-5f);
        float ha = (ta - mu) * inv * sP[64 + c0]     + sP[128 + c0];
        float hb = (tb - mu) * inv * sP[64 + c0 + 1] + sP[128 + c0 + 1];
        B[c0] = ha; B[c0 + 1] = hb;
        __syncwarp();

        float qa = 0.f, qb = 0.f, ka = 0.f, kb = 0.f, va = 0.f, vb = 0.f;
        #pragma unroll 16
        for (int h = 0; h < 64; h++) {
            float hv = B[h];
            float2 w1 = wQ[h * 32 + lane];
            float2 w2 = wK[h * 32 + lane];
            float2 w3 = wV[h * 32 + lane];
            qa = fmaf(hv, w1.x, qa); qb = fmaf(hv, w1.y, qb);
            ka = fmaf(hv, w2.x, ka); kb = fmaf(hv, w2.y, kb);
            va = fmaf(hv, w3.x, va); vb = fmaf(hv, w3.y, vb);
        }
        *(float2*)(g_q + (size_t)n * 64 + c0) = make_float2(qa, qb);
        *(float2*)(g_k + (size_t)n * 64 + c0) = make_float2(ka, kb);
        *(float2*)(g_v + (size_t)n * 64 + c0) = make_float2(va, vb);
        __syncwarp();
    }
}

// ---------------------------------------------------------------------------
// Edge kernel: warp processes a 16-edge tile with mma.sync m16n8k16 bf16.
// Each fp32 GEMM done as 3 bf16 mmas (hi*hi + lo*hi + hi*lo), error ~2^-17.
// D-fragment layout (cols {2m,2m+1}) == A-fragment layout for k16 bf16, so
// inter-layer handoff needs only relu + bf16 split (no shuffles, no smem).
//
// Fragment maps (lane: r0 = lane>>2, m = lane&3, r1 = r0+8):
//   A (16x64): kk-tile covers k-cols 16kk+...: a0=(r0,{2m,2m+1}), a1=(r1,..),
//              a2=(r0,{2m+8,2m+9}), a3=(r1,..)   [each reg = bf16x2]
//   B (64x64 weights): (kk,nn) frag: b0 = W[16kk+2m..+1][8nn + lane>>2],
//              b1 = W[16kk+2m+8..+9][..]; hi/lo stored as uint4 per lane.
//   D (16x64): nn-group: d0=(r0,8nn+2m), d1=(r0,+1), d2=(r1,..), d3=(r1,+1)
// ---------------------------------------------------------------------------
struct EdgeGemmSmem {
    // 3 layers x 4096 u32 of packed bf16 weight fragments
    // + 64 float4 (pnW1 cols + pnb1) + 3*64 f32 biases
};
#define EDGE_SMEM (3 * 4096 * 4 + 64 * 16 + 3 * 64 * 4)   // 50944 B

__device__ __forceinline__ void gemm16(float D[8][4],
        const unsigned Ah[4][4], const unsigned Al[4][4],
        const unsigned* __restrict__ sW, const float* __restrict__ bias, int lane) {
    const int m = lane & 3;
    #pragma unroll
    for (int nn = 0; nn < 8; nn++) {
        float2 b = *(const float2*)(bias + nn * 8 + 2 * m);
        D[nn][0] = b.x; D[nn][1] = b.y; D[nn][2] = b.x; D[nn][3] = b.y;
        #pragma unroll
        for (int kk = 0; kk < 4; kk++) {
            uint4 B = *(const uint4*)(sW + ((nn * 4 + kk) * 32 + lane) * 4);
            mma_bf16(D[nn], Ah[kk][0], Ah[kk][1], Ah[kk][2], Ah[kk][3], B.x, B.y);
            mma_bf16(D[nn], Al[kk][0], Al[kk][1], Al[kk][2], Al[kk][3], B.x, B.y);
            mma_bf16(D[nn], Ah[kk][0], Ah[kk][1], Ah[kk][2], Ah[kk][3], B.z, B.w);
        }
    }
}

__global__ void __launch_bounds__(128, 4) k_edge(
        int E, const int* __restrict__ ei, const float* __restrict__ pos,
        const float* __restrict__ pnW1, const float* __restrict__ pnb1,
        const float* __restrict__ pnW2, const float* __restrict__ pnb2,
        const float* __restrict__ anW1, const float* __restrict__ anb1,
        const float* __restrict__ anW2, const float* __restrict__ anb2) {
    extern __shared__ unsigned smu[];
    unsigned* sWL = smu;                          // 3 * 4096 u32
    float4*  sW1  = (float4*)(smu + 12288);       // 64 float4: {W1[0][c],W1[1][c],W1[2][c],b1[c]}
    float*   sB   = (float*)(smu + 12288 + 256);  // [0]=pnb2, [64]=anb1, [128]=anb2

    // ---- one-time weight prep: fp32 -> hi/lo bf16 fragments -------------
    const float* Wg0 = pnW2;
    const float* Wg1 = anW1;
    const float* Wg2 = anW2;
    #pragma unroll 1
    for (int L = 0; L < 3; L++) {
        const float* W = (L == 0) ? Wg0 : (L == 1) ? Wg1 : Wg2;
        unsigned* dstW = sWL + L * 4096;
        for (int i = threadIdx.x; i < 4096; i += 128) {
            int h = i >> 6, c = i & 63;
            float w = W[i];
            unsigned short hb = __bfloat16_as_ushort(__float2bfloat16(w));
            float hif = __uint_as_float((unsigned)hb << 16);
            unsigned short lb = __bfloat16_as_ushort(__float2bfloat16(w - hif));
            int kk = h >> 4, hh = h & 15;
            int e = hh & 1, mm = (hh >> 1) & 3, rg = hh >> 3;
            int nn = c >> 3, q = c & 7, ln = q * 4 + mm;
            unsigned short* p16 = (unsigned short*)(dstW + ((nn * 4 + kk) * 32 + ln) * 4);
            p16[rg * 2 + e]     = hb;
            p16[4 + rg * 2 + e] = lb;
        }
    }
    if (threadIdx.x < 64) {
        int c = threadIdx.x;
        sW1[c] = make_float4(pnW1[c], pnW1[64 + c], pnW1[128 + c], pnb1[c]);
        sB[c]        = pnb2[c];
        sB[64 + c]   = anb1[c];
        sB[128 + c]  = anb2[c];
    }
    __syncthreads();

    const int lane = threadIdx.x & 31, warp = threadIdx.x >> 5;
    const int r0 = lane >> 2, m = lane & 3;
    const int gw = blockIdx.x * 4 + warp;
    const int nw = gridDim.x * 4;
    const int ntiles = (E + 15) >> 4;

    unsigned Ah[4][4], Al[4][4];
    float D[8][4];
    float Dlt[8][4];

    for (int t = gw; t < ntiles; t += nw) {
        const int base = t << 4;
        const int er0 = base + r0, er1 = base + r0 + 8;
        const bool ok0 = er0 < E, ok1 = er1 < E;
        const int ec0 = ok0 ? er0 : E - 1;
        const int ec1 = ok1 ? er1 : E - 1;
        const int s0 = ei[ec0],     s1 = ei[ec1];
        const int d0 = ei[E + ec0], d1 = ei[E + ec1];

        const float p00 = pos[d0 * 3 + 0] - pos[s0 * 3 + 0];
        const float p01 = pos[d0 * 3 + 1] - pos[s0 * 3 + 1];
        const float p02 = pos[d0 * 3 + 2] - pos[s0 * 3 + 2];
        const float p10 = pos[d1 * 3 + 0] - pos[s1 * 3 + 0];
        const float p11 = pos[d1 * 3 + 1] - pos[s1 * 3 + 1];
        const float p12 = pos[d1 * 3 + 2] - pos[s1 * 3 + 2];

        // ---- pos MLP layer 1 (3 -> 64), fp32, direct into A fragments ----
        #pragma unroll
        for (int kk = 0; kk < 4; kk++) {
            const int cb = kk * 16 + 2 * m;
            float4 wA = sW1[cb],     wB = sW1[cb + 1];
            float4 wC = sW1[cb + 8], wD = sW1[cb + 9];
            float h00 = fmaxf(fmaf(p02, wA.z, fmaf(p01, wA.y, fmaf(p00, wA.x, wA.w))), 0.f);
            float h01 = fmaxf(fmaf(p02, wB.z, fmaf(p01, wB.y, fmaf(p00, wB.x, wB.w))), 0.f);
            float h10 = fmaxf(fmaf(p12, wA.z, fmaf(p11, wA.y, fmaf(p10, wA.x, wA.w))), 0.f);
            float h11 = fmaxf(fmaf(p12, wB.z, fmaf(p11, wB.y, fmaf(p10, wB.x, wB.w))), 0.f);
            float h08 = fmaxf(fmaf(p02, wC.z, fmaf(p01, wC.y, fmaf(p00, wC.x, wC.w))), 0.f);
            float h09 = fmaxf(fmaf(p02, wD.z, fmaf(p01, wD.y, fmaf(p00, wD.x, wD.w))), 0.f);
            float h18 = fmaxf(fmaf(p12, wC.z, fmaf(p11, wC.y, fmaf(p10, wC.x, wC.w))), 0.f);
            float h19 = fmaxf(fmaf(p12, wD.z, fmaf(p11, wD.y, fmaf(p10, wD.x, wD.w))), 0.f);
            split_pair(h00, h01, Ah[kk][0], Al[kk][0]);
            split_pair(h10, h11, Ah[kk][1], Al[kk][1]);
            split_pair(h08, h09, Ah[kk][2], Al[kk][2]);
            split_pair(h18, h19, Ah[kk][3], Al[kk][3]);
        }

        // ---- GEMM1: delta = relu(H1 @ pnW2 + pnb2) -----------------------
        gemm16(D, Ah, Al, sWL, sB, lane);
        #pragma unroll
        for (int nn = 0; nn < 8; nn++) {
            Dlt[nn][0] = fmaxf(D[nn][0], 0.f);
            Dlt[nn][1] = fmaxf(D[nn][1], 0.f);
            Dlt[nn][2] = fmaxf(D[nn][2], 0.f);
            Dlt[nn][3] = fmaxf(D[nn][3], 0.f);
        }

        // ---- A2 = q[d] - k[s] + delta ------------------------------------
        #pragma unroll
        for (int kk = 0; kk < 4; kk++) {
            const int cb = kk * 16 + 2 * m;
            float2 qa = *(const float2*)(g_q + (size_t)d0 * 64 + cb);
            float2 ka = *(const float2*)(g_k + (size_t)s0 * 64 + cb);
            float2 qb = *(const float2*)(g_q + (size_t)d1 * 64 + cb);
            float2 kb = *(const float2*)(g_k + (size_t)s1 * 64 + cb);
            float2 qc = *(const float2*)(g_q + (size_t)d0 * 64 + cb + 8);
            float2 kc = *(const float2*)(g_k + (size_t)s0 * 64 + cb + 8);
            float2 qd = *(const float2*)(g_q + (size_t)d1 * 64 + cb + 8);
            float2 kd = *(const float2*)(g_k + (size_t)s1 * 64 + cb + 8);
            split_pair(qa.x - ka.x + Dlt[2*kk][0],   qa.y - ka.y + Dlt[2*kk][1],   Ah[kk][0], Al[kk][0]);
            split_pair(qb.x - kb.x + Dlt[2*kk][2],   qb.y - kb.y + Dlt[2*kk][3],   Ah[kk][1], Al[kk][1]);
            split_pair(qc.x - kc.x + Dlt[2*kk+1][0], qc.y - kc.y + Dlt[2*kk+1][1], Ah[kk][2], Al[kk][2]);
            split_pair(qd.x - kd.x + Dlt[2*kk+1][2], qd.y - kd.y + Dlt[2*kk+1][3], Ah[kk][3], Al[kk][3]);
        }

        // ---- GEMM2: G = relu(A2 @ anW1 + anb1) ---------------------------
        gemm16(D, Ah, Al, sWL + 4096, sB + 64, lane);
        #pragma unroll
        for (int kk = 0; kk < 4; kk++) {
            split_pair(fmaxf(D[2*kk][0], 0.f),   fmaxf(D[2*kk][1], 0.f),   Ah[kk][0], Al[kk][0]);
            split_pair(fmaxf(D[2*kk][2], 0.f),   fmaxf(D[2*kk][3], 0.f),   Ah[kk][1], Al[kk][1]);
            split_pair(fmaxf(D[2*kk+1][0], 0.f), fmaxf(D[2*kk+1][1], 0.f), Ah[kk][2], Al[kk][2]);
            split_pair(fmaxf(D[2*kk+1][2], 0.f), fmaxf(D[2*kk+1][3], 0.f), Ah[kk][3], Al[kk][3]);
        }

        // ---- GEMM3: alpha = G @ anW2 + anb2 ------------------------------
        gemm16(D, Ah, Al, sWL + 8192, sB + 128, lane);

        // ---- epilogue: e = exp(relu(alpha)); RED {e*(v+delta), e} --------
        #pragma unroll
        for (int nn = 0; nn < 8; nn++) {
            const int cb = nn * 8 + 2 * m;
            float e00 = __expf(fmaxf(D[nn][0], 0.f));
            float e01 = __expf(fmaxf(D[nn][1], 0.f));
            float e10 = __expf(fmaxf(D[nn][2], 0.f));
            float e11 = __expf(fmaxf(D[nn][3], 0.f));
            float2 v0 = *(const float2*)(g_v + (size_t)s0 * 64 + cb);
            float2 v1 = *(const float2*)(g_v + (size_t)s1 * 64 + cb);
            if (ok0)
                red_add_v4(g_acc + (size_t)d0 * 128 + cb * 2,
                           e00 * (v0.x + Dlt[nn][0]), e00,
                           e01 * (v0.y + Dlt[nn][1]), e01);
            if (ok1)
                red_add_v4(g_acc + (size_t)d1 * 128 + cb * 2,
                           e10 * (v1.x + Dlt[nn][2]), e10,
                           e11 * (v1.y + Dlt[nn][3]), e11);
        }
    }
}

// ---------------------------------------------------------------------------
// Output: out = relu((num / (den + 1e-16)) @ W_out + b_out)  (round-1 variant)
// ---------------------------------------------------------------------------
__global__ void k_out(int N, const float* __restrict__ W_out, const float* __restrict__ b_out,
                      float* __restrict__ out) {
    extern __shared__ float sm[];
    float* sW   = sm;
    float* sb   = sm + 4096;
    float* sScr = sm + 4160;

    for (int i = threadIdx.x; i < 4096; i += blockDim.x) sW[i] = W_out[i];
    if (threadIdx.x < 64) sb[threadIdx.x] = b_out[threadIdx.x];
    __syncthreads();

    const int warp = threadIdx.x >> 5, lane = threadIdx.x & 31;
    const int c0 = lane * 2;
    float* A = sScr + warp * 64;
    const int gw = blockIdx.x * (blockDim.x >> 5) + warp;
    const int nw = gridDim.x * (blockDim.x >> 5);
    const float2* wO = (const float2*)sW;

    for (int n = gw; n < N; n += nw) {
        float4 ld = *(const float4*)(g_acc + (size_t)n * 128 + lane * 4);
        A[c0]     = ld.x / (ld.y + 1e-16f);
        A[c0 + 1] = ld.z / (ld.w + 1e-16f);
        __syncwarp();
        float oa = sb[c0], ob = sb[c0 + 1];
        #pragma unroll 16
        for (int h = 0; h < 64; h++) {
            float2 w = wO[h * 32 + lane];
            float hv = A[h];
            oa = fmaf(hv, w.x, oa); ob = fmaf(hv, w.y, ob);
        }
        *(float2*)(out + (size_t)n * 64 + c0) = make_float2(fmaxf(oa, 0.f), fmaxf(ob, 0.f));
        __syncwarp();
    }
}

// ---------------------------------------------------------------------------

#define NODE_SMEM ((16384 + 192 + 8 * 128) * 4)
#define OUT_SMEM  ((4096 + 64 + 8 * 64) * 4)

extern "C" void kernel_launch(void* const* d_in, const int* in_sizes, int n_in,
                              void* d_out, int out_size) {
    const float* x     = (const float*)d_in[0];
    const float* pos   = (const float*)d_in[1];
    const int*   ei    = (const int*)d_in[2];
    const float* W_in  = (const float*)d_in[3];
    const float* b_in  = (const float*)d_in[4];
    const float* ln_g  = (const float*)d_in[5];
    const float* ln_b  = (const float*)d_in[6];
    const float* W_lin = (const float*)d_in[7];
    const float* W_src = (const float*)d_in[8];
    const float* W_dst = (const float*)d_in[9];
    const float* pnW1  = (const float*)d_in[10];
    const float* pnb1  = (const float*)d_in[11];
    const float* pnW2  = (const float*)d_in[12];
    const float* pnb2  = (const float*)d_in[13];
    const float* anW1  = (const float*)d_in[14];
    const float* anb1  = (const float*)d_in[15];
    const float* anW2  = (const float*)d_in[16];
    const float* anb2  = (const float*)d_in[17];
    const float* W_out = (const float*)d_in[18];
    const float* b_out = (const float*)d_in[19];

    const int N = in_sizes[0] / 64;
    const int E = in_sizes[2] / 2;

    cudaFuncSetAttribute(k_node, cudaFuncAttributeMaxDynamicSharedMemorySize, NODE_SMEM);
    cudaFuncSetAttribute(k_edge, cudaFuncAttributeMaxDynamicSharedMemorySize, EDGE_SMEM);

    const int n4 = N * 32;
    k_zero<<<(n4 + 255) / 256, 256>>>(n4);
    k_node<<<444, 256, NODE_SMEM>>>(N, x, W_in, b_in, ln_g, ln_b, W_lin, W_src, W_dst);
    k_edge<<<592, 128, EDGE_SMEM>>>(E, ei, pos, pnW1, pnb1, pnW2, pnb2,
                                    anW1, anb1, anW2, anb2);
    k_out<<<592, 256, OUT_SMEM>>>(N, W_out, b_out, (float*)d_out);
}

// round 4
// speedup vs baseline: 2.8929x; 1.2453x over previous
#include <cuda_runtime.h>
#include <cuda_bf16.h>

#define CDIM 64
#define MAXN 100000

__device__ float g_q[MAXN * CDIM];
__device__ float g_k[MAXN * CDIM];
__device__ float g_v[MAXN * CDIM];
__device__ float g_acc[MAXN * CDIM * 2];   // [node][chan][{num, denom}]

__device__ __forceinline__ void red_add_v4(float* p, float a, float b, float c, float d) {
    asm volatile("red.global.add.v4.f32 [%0], {%1, %2, %3, %4};"
                 :: "l"(p), "f"(a), "f"(b), "f"(c), "f"(d) : "memory");
}
// pack two f32 into bf16x2: low 16 bits = lo_val, high = hi_val
__device__ __forceinline__ unsigned pack_bf16x2(float lo_val, float hi_val) {
    unsigned r;
    asm("cvt.rn.bf16x2.f32 %0, %1, %2;" : "=r"(r) : "f"(hi_val), "f"(lo_val));
    return r;
}
__device__ __forceinline__ float bfx2_lo_f32(unsigned p) { return __uint_as_float(p << 16); }
__device__ __forceinline__ float bfx2_hi_f32(unsigned p) { return __uint_as_float(p & 0xFFFF0000u); }

// split (v0,v1) into hi/lo bf16x2 pairs: v ~= hi + lo with ~2^-17 residual
__device__ __forceinline__ void split_pair(float v0, float v1, unsigned& hi, unsigned& lo) {
    hi = pack_bf16x2(v0, v1);
    float r0 = v0 - bfx2_lo_f32(hi);
    float r1 = v1 - bfx2_hi_f32(hi);
    lo = pack_bf16x2(r0, r1);
}

__device__ __forceinline__ void mma_bf16(float d[4],
        unsigned a0, unsigned a1, unsigned a2, unsigned a3,
        unsigned b0, unsigned b1) {
    asm("mma.sync.aligned.m16n8k16.row.col.f32.bf16.bf16.f32 "
        "{%0,%1,%2,%3}, {%4,%5,%6,%7}, {%8,%9}, {%0,%1,%2,%3};"
        : "+f"(d[0]), "+f"(d[1]), "+f"(d[2]), "+f"(d[3])
        : "r"(a0), "r"(a1), "r"(a2), "r"(a3), "r"(b0), "r"(b1));
}

// fp32 (64x64) weight matrix -> hi/lo bf16 B-fragments in smem
__device__ __forceinline__ void prep_weights(const float* __restrict__ W,
                                             unsigned* __restrict__ dstW,
                                             int tcount, int tid) {
    for (int i = tid; i < 4096; i += tcount) {
        int h = i >> 6, c = i & 63;
        float w = W[i];
        unsigned short hb = __bfloat16_as_ushort(__float2bfloat16(w));
        float hif = __uint_as_float((unsigned)hb << 16);
        unsigned short lb = __bfloat16_as_ushort(__float2bfloat16(w - hif));
        int kk = h >> 4, hh = h & 15;
        int e = hh & 1, mm = (hh >> 1) & 3, rg = hh >> 3;
        int nn = c >> 3, q = c & 7, ln = q * 4 + mm;
        unsigned short* p16 = (unsigned short*)(dstW + ((nn * 4 + kk) * 32 + ln) * 4);
        p16[rg * 2 + e]     = hb;
        p16[4 + rg * 2 + e] = lb;
    }
}

// 16xCx64 GEMM tile: 3-mma bf16 split per (nn,kk). D layout:
// D[nn][0]=(r0,8nn+2m) [1]=(r0,+1) [2]=(r1,8nn+2m) [3]=(r1,+1)
template<bool BIAS>
__device__ __forceinline__ void gemm16(float D[8][4],
        const unsigned Ah[4][4], const unsigned Al[4][4],
        const unsigned* __restrict__ sW, const float* __restrict__ bias, int lane) {
    const int m = lane & 3;
    #pragma unroll
    for (int nn = 0; nn < 8; nn++) {
        if (BIAS) {
            float2 b = *(const float2*)(bias + nn * 8 + 2 * m);
            D[nn][0] = b.x; D[nn][1] = b.y; D[nn][2] = b.x; D[nn][3] = b.y;
        } else {
            D[nn][0] = 0.f; D[nn][1] = 0.f; D[nn][2] = 0.f; D[nn][3] = 0.f;
        }
        #pragma unroll
        for (int kk = 0; kk < 4; kk++) {
            uint4 B = *(const uint4*)(sW + ((nn * 4 + kk) * 32 + lane) * 4);
            mma_bf16(D[nn], Ah[kk][0], Ah[kk][1], Ah[kk][2], Ah[kk][3], B.x, B.y);
            mma_bf16(D[nn], Al[kk][0], Al[kk][1], Al[kk][2], Al[kk][3], B.x, B.y);
            mma_bf16(D[nn], Ah[kk][0], Ah[kk][1], Ah[kk][2], Ah[kk][3], B.z, B.w);
        }
    }
}

// ---------------------------------------------------------------------------
// Node kernel (tensorized): 16 nodes per warp tile.
// H = LN(relu(X@W_in+b)); q=H@W_dst; k=H@W_src; v=H@W_lin. Also zeros g_acc.
// ---------------------------------------------------------------------------
#define NODE_SMEM (4 * 4096 * 4 + 192 * 4)
__global__ void __launch_bounds__(256, 2) k_node(
        int N, const float* __restrict__ x,
        const float* __restrict__ W_in, const float* __restrict__ b_in,
        const float* __restrict__ ln_g, const float* __restrict__ ln_b,
        const float* __restrict__ W_lin, const float* __restrict__ W_src,
        const float* __restrict__ W_dst) {
    extern __shared__ unsigned smu[];
    unsigned* sW = smu;                        // [W_in | Wq | Wk | Wv]
    float* sP = (float*)(smu + 16384);         // b_in[64], ln_g[64], ln_b[64]

    prep_weights(W_in,  sW,         blockDim.x, threadIdx.x);
    prep_weights(W_dst, sW + 4096,  blockDim.x, threadIdx.x);
    prep_weights(W_src, sW + 8192,  blockDim.x, threadIdx.x);
    prep_weights(W_lin, sW + 12288, blockDim.x, threadIdx.x);
    if (threadIdx.x < 64) {
        sP[threadIdx.x]       = b_in[threadIdx.x];
        sP[64 + threadIdx.x]  = ln_g[threadIdx.x];
        sP[128 + threadIdx.x] = ln_b[threadIdx.x];
    }
    __syncthreads();

    const int lane = threadIdx.x & 31, warp = threadIdx.x >> 5;
    const int r0 = lane >> 2, m = lane & 3;
    const int gw = blockIdx.x * (blockDim.x >> 5) + warp;
    const int nw = gridDim.x * (blockDim.x >> 5);
    const int ntiles = (N + 15) >> 4;

    unsigned Ah[4][4], Al[4][4];
    float D[8][4];

    for (int t = gw; t < ntiles; t += nw) {
        const int base = t << 4;
        const int row0 = base + r0, row1 = base + r0 + 8;
        const bool ok0 = row0 < N, ok1 = row1 < N;
        const int rr0 = ok0 ? row0 : N - 1;
        const int rr1 = ok1 ? row1 : N - 1;

        // gather X fragments
        #pragma unroll
        for (int kk = 0; kk < 4; kk++) {
            const int cb = kk * 16 + 2 * m;
            float2 xa = *(const float2*)(x + (size_t)rr0 * 64 + cb);
            float2 xb = *(const float2*)(x + (size_t)rr1 * 64 + cb);
            float2 xc = *(const float2*)(x + (size_t)rr0 * 64 + cb + 8);
            float2 xd = *(const float2*)(x + (size_t)rr1 * 64 + cb + 8);
            split_pair(xa.x, xa.y, Ah[kk][0], Al[kk][0]);
            split_pair(xb.x, xb.y, Ah[kk][1], Al[kk][1]);
            split_pair(xc.x, xc.y, Ah[kk][2], Al[kk][2]);
            split_pair(xd.x, xd.y, Ah[kk][3], Al[kk][3]);
        }

        // H = relu(X@W_in + b_in)
        gemm16<true>(D, Ah, Al, sW, sP, lane);
        #pragma unroll
        for (int nn = 0; nn < 8; nn++) {
            D[nn][0] = fmaxf(D[nn][0], 0.f); D[nn][1] = fmaxf(D[nn][1], 0.f);
            D[nn][2] = fmaxf(D[nn][2], 0.f); D[nn][3] = fmaxf(D[nn][3], 0.f);
        }

        // LayerNorm: row stats via quad (m-group) reduction
        float s0 = 0.f, q0 = 0.f, s1 = 0.f, q1 = 0.f;
        #pragma unroll
        for (int nn = 0; nn < 8; nn++) {
            s0 += D[nn][0] + D[nn][1];
            q0 += D[nn][0] * D[nn][0] + D[nn][1] * D[nn][1];
            s1 += D[nn][2] + D[nn][3];
            q1 += D[nn][2] * D[nn][2] + D[nn][3] * D[nn][3];
        }
        #pragma unroll
        for (int off = 1; off <= 2; off <<= 1) {
            s0 += __shfl_xor_sync(0xffffffffu, s0, off);
            q0 += __shfl_xor_sync(0xffffffffu, q0, off);
            s1 += __shfl_xor_sync(0xffffffffu, s1, off);
            q1 += __shfl_xor_sync(0xffffffffu, q1, off);
        }
        float mu0 = s0 * 0.015625f, mu1 = s1 * 0.015625f;
        float inv0 = rsqrtf(q0 * 0.015625f - mu0 * mu0 + 1e-5f);
        float inv1 = rsqrtf(q1 * 0.015625f - mu1 * mu1 + 1e-5f);

        // normalize + handoff into A fragments (D-layout == A-layout)
        #pragma unroll
        for (int kk = 0; kk < 4; kk++) {
            const int c = kk * 16 + 2 * m;
            float2 ga = *(const float2*)(sP + 64 + c);
            float2 ba = *(const float2*)(sP + 128 + c);
            float2 gb = *(const float2*)(sP + 64 + c + 8);
            float2 bb = *(const float2*)(sP + 128 + c + 8);
            float h00 = (D[2*kk][0]   - mu0) * inv0 * ga.x + ba.x;
            float h01 = (D[2*kk][1]   - mu0) * inv0 * ga.y + ba.y;
            float h10 = (D[2*kk][2]   - mu1) * inv1 * ga.x + ba.x;
            float h11 = (D[2*kk][3]   - mu1) * inv1 * ga.y + ba.y;
            float h08 = (D[2*kk+1][0] - mu0) * inv0 * gb.x + bb.x;
            float h09 = (D[2*kk+1][1] - mu0) * inv0 * gb.y + bb.y;
            float h18 = (D[2*kk+1][2] - mu1) * inv1 * gb.x + bb.x;
            float h19 = (D[2*kk+1][3] - mu1) * inv1 * gb.y + bb.y;
            split_pair(h00, h01, Ah[kk][0], Al[kk][0]);
            split_pair(h10, h11, Ah[kk][1], Al[kk][1]);
            split_pair(h08, h09, Ah[kk][2], Al[kk][2]);
            split_pair(h18, h19, Ah[kk][3], Al[kk][3]);
        }

        // q / k / v GEMMs + stores
        gemm16<false>(D, Ah, Al, sW + 4096, nullptr, lane);
        #pragma unroll
        for (int nn = 0; nn < 8; nn++) {
            const int c = nn * 8 + 2 * m;
            if (ok0) *(float2*)(g_q + (size_t)row0 * 64 + c) = make_float2(D[nn][0], D[nn][1]);
            if (ok1) *(float2*)(g_q + (size_t)row1 * 64 + c) = make_float2(D[nn][2], D[nn][3]);
        }
        gemm16<false>(D, Ah, Al, sW + 8192, nullptr, lane);
        #pragma unroll
        for (int nn = 0; nn < 8; nn++) {
            const int c = nn * 8 + 2 * m;
            if (ok0) *(float2*)(g_k + (size_t)row0 * 64 + c) = make_float2(D[nn][0], D[nn][1]);
            if (ok1) *(float2*)(g_k + (size_t)row1 * 64 + c) = make_float2(D[nn][2], D[nn][3]);
        }
        gemm16<false>(D, Ah, Al, sW + 12288, nullptr, lane);
        #pragma unroll
        for (int nn = 0; nn < 8; nn++) {
            const int c = nn * 8 + 2 * m;
            if (ok0) *(float2*)(g_v + (size_t)row0 * 64 + c) = make_float2(D[nn][0], D[nn][1]);
            if (ok1) *(float2*)(g_v + (size_t)row1 * 64 + c) = make_float2(D[nn][2], D[nn][3]);
        }

        // zero g_acc for these 16 nodes (512 float4)
        float4* accz = (float4*)(g_acc + (size_t)base * 128);
        #pragma unroll
        for (int i = 0; i < 16; i++) {
            int idx = i * 32 + lane;
            if (base + (idx >> 5) < N)
                accz[idx] = make_float4(0.f, 0.f, 0.f, 0.f);
        }
    }
}

// ---------------------------------------------------------------------------
// Edge kernel (round-3 tensorized version, tile-range parameterized)
// ---------------------------------------------------------------------------
#define EDGE_SMEM (3 * 4096 * 4 + 64 * 16 + 3 * 64 * 4)   // 50944 B

__global__ void __launch_bounds__(128, 4) k_edge(
        int E, int tile0, int tile1,
        const int* __restrict__ ei, const float* __restrict__ pos,
        const float* __restrict__ pnW1, const float* __restrict__ pnb1,
        const float* __restrict__ pnW2, const float* __restrict__ pnb2,
        const float* __restrict__ anW1, const float* __restrict__ anb1,
        const float* __restrict__ anW2, const float* __restrict__ anb2) {
    extern __shared__ unsigned smu[];
    unsigned* sWL = smu;                          // 3 * 4096 u32
    float4*  sW1  = (float4*)(smu + 12288);       // {W1[0][c],W1[1][c],W1[2][c],b1[c]}
    float*   sB   = (float*)(smu + 12288 + 256);  // pnb2 | anb1 | anb2

    prep_weights(pnW2, sWL,        128, threadIdx.x);
    prep_weights(anW1, sWL + 4096, 128, threadIdx.x);
    prep_weights(anW2, sWL + 8192, 128, threadIdx.x);
    if (threadIdx.x < 64) {
        int c = threadIdx.x;
        sW1[c] = make_float4(pnW1[c], pnW1[64 + c], pnW1[128 + c], pnb1[c]);
        sB[c]        = pnb2[c];
        sB[64 + c]   = anb1[c];
        sB[128 + c]  = anb2[c];
    }
    __syncthreads();

    const int lane = threadIdx.x & 31, warp = threadIdx.x >> 5;
    const int r0 = lane >> 2, m = lane & 3;
    const int gw = blockIdx.x * 4 + warp;
    const int nw = gridDim.x * 4;

    unsigned Ah[4][4], Al[4][4];
    float D[8][4];
    float Dlt[8][4];

    for (int t = tile0 + gw; t < tile1; t += nw) {
        const int base = t << 4;
        const int er0 = base + r0, er1 = base + r0 + 8;
        const bool ok0 = er0 < E, ok1 = er1 < E;
        const int ec0 = ok0 ? er0 : E - 1;
        const int ec1 = ok1 ? er1 : E - 1;
        const int s0 = ei[ec0],     s1 = ei[ec1];
        const int d0 = ei[E + ec0], d1 = ei[E + ec1];

        const float p00 = pos[d0 * 3 + 0] - pos[s0 * 3 + 0];
        const float p01 = pos[d0 * 3 + 1] - pos[s0 * 3 + 1];
        const float p02 = pos[d0 * 3 + 2] - pos[s0 * 3 + 2];
        const float p10 = pos[d1 * 3 + 0] - pos[s1 * 3 + 0];
        const float p11 = pos[d1 * 3 + 1] - pos[s1 * 3 + 1];
        const float p12 = pos[d1 * 3 + 2] - pos[s1 * 3 + 2];

        // pos MLP layer 1 (3 -> 64), fp32, direct into A fragments
        #pragma unroll
        for (int kk = 0; kk < 4; kk++) {
            const int cb = kk * 16 + 2 * m;
            float4 wA = sW1[cb],     wB = sW1[cb + 1];
            float4 wC = sW1[cb + 8], wD = sW1[cb + 9];
            float h00 = fmaxf(fmaf(p02, wA.z, fmaf(p01, wA.y, fmaf(p00, wA.x, wA.w))), 0.f);
            float h01 = fmaxf(fmaf(p02, wB.z, fmaf(p01, wB.y, fmaf(p00, wB.x, wB.w))), 0.f);
            float h10 = fmaxf(fmaf(p12, wA.z, fmaf(p11, wA.y, fmaf(p10, wA.x, wA.w))), 0.f);
            float h11 = fmaxf(fmaf(p12, wB.z, fmaf(p11, wB.y, fmaf(p10, wB.x, wB.w))), 0.f);
            float h08 = fmaxf(fmaf(p02, wC.z, fmaf(p01, wC.y, fmaf(p00, wC.x, wC.w))), 0.f);
            float h09 = fmaxf(fmaf(p02, wD.z, fmaf(p01, wD.y, fmaf(p00, wD.x, wD.w))), 0.f);
            float h18 = fmaxf(fmaf(p12, wC.z, fmaf(p11, wC.y, fmaf(p10, wC.x, wC.w))), 0.f);
            float h19 = fmaxf(fmaf(p12, wD.z, fmaf(p11, wD.y, fmaf(p10, wD.x, wD.w))), 0.f);
            split_pair(h00, h01, Ah[kk][0], Al[kk][0]);
            split_pair(h10, h11, Ah[kk][1], Al[kk][1]);
            split_pair(h08, h09, Ah[kk][2], Al[kk][2]);
            split_pair(h18, h19, Ah[kk][3], Al[kk][3]);
        }

        // GEMM1: delta = relu(H1 @ pnW2 + pnb2)
        gemm16<true>(D, Ah, Al, sWL, sB, lane);
        #pragma unroll
        for (int nn = 0; nn < 8; nn++) {
            Dlt[nn][0] = fmaxf(D[nn][0], 0.f);
            Dlt[nn][1] = fmaxf(D[nn][1], 0.f);
            Dlt[nn][2] = fmaxf(D[nn][2], 0.f);
            Dlt[nn][3] = fmaxf(D[nn][3], 0.f);
        }

        // A2 = q[d] - k[s] + delta
        #pragma unroll
        for (int kk = 0; kk < 4; kk++) {
            const int cb = kk * 16 + 2 * m;
            float2 qa = *(const float2*)(g_q + (size_t)d0 * 64 + cb);
            float2 ka = *(const float2*)(g_k + (size_t)s0 * 64 + cb);
            float2 qb = *(const float2*)(g_q + (size_t)d1 * 64 + cb);
            float2 kb = *(const float2*)(g_k + (size_t)s1 * 64 + cb);
            float2 qc = *(const float2*)(g_q + (size_t)d0 * 64 + cb + 8);
            float2 kc = *(const float2*)(g_k + (size_t)s0 * 64 + cb + 8);
            float2 qd = *(const float2*)(g_q + (size_t)d1 * 64 + cb + 8);
            float2 kd = *(const float2*)(g_k + (size_t)s1 * 64 + cb + 8);
            split_pair(qa.x - ka.x + Dlt[2*kk][0],   qa.y - ka.y + Dlt[2*kk][1],   Ah[kk][0], Al[kk][0]);
            split_pair(qb.x - kb.x + Dlt[2*kk][2],   qb.y - kb.y + Dlt[2*kk][3],   Ah[kk][1], Al[kk][1]);
            split_pair(qc.x - kc.x + Dlt[2*kk+1][0], qc.y - kc.y + Dlt[2*kk+1][1], Ah[kk][2], Al[kk][2]);
            split_pair(qd.x - kd.x + Dlt[2*kk+1][2], qd.y - kd.y + Dlt[2*kk+1][3], Ah[kk][3], Al[kk][3]);
        }

        // GEMM2: G = relu(A2 @ anW1 + anb1)
        gemm16<true>(D, Ah, Al, sWL + 4096, sB + 64, lane);
        #pragma unroll
        for (int kk = 0; kk < 4; kk++) {
            split_pair(fmaxf(D[2*kk][0], 0.f),   fmaxf(D[2*kk][1], 0.f),   Ah[kk][0], Al[kk][0]);
            split_pair(fmaxf(D[2*kk][2], 0.f),   fmaxf(D[2*kk][3], 0.f),   Ah[kk][1], Al[kk][1]);
            split_pair(fmaxf(D[2*kk+1][0], 0.f), fmaxf(D[2*kk+1][1], 0.f), Ah[kk][2], Al[kk][2]);
            split_pair(fmaxf(D[2*kk+1][2], 0.f), fmaxf(D[2*kk+1][3], 0.f), Ah[kk][3], Al[kk][3]);
        }

        // GEMM3: alpha = G @ anW2 + anb2
        gemm16<true>(D, Ah, Al, sWL + 8192, sB + 128, lane);

        // epilogue: e = exp(relu(alpha)); RED {e*(v+delta), e}
        #pragma unroll
        for (int nn = 0; nn < 8; nn++) {
            const int cb = nn * 8 + 2 * m;
            float e00 = __expf(fmaxf(D[nn][0], 0.f));
            float e01 = __expf(fmaxf(D[nn][1], 0.f));
            float e10 = __expf(fmaxf(D[nn][2], 0.f));
            float e11 = __expf(fmaxf(D[nn][3], 0.f));
            float2 v0 = *(const float2*)(g_v + (size_t)s0 * 64 + cb);
            float2 v1 = *(const float2*)(g_v + (size_t)s1 * 64 + cb);
            if (ok0)
                red_add_v4(g_acc + (size_t)d0 * 128 + cb * 2,
                           e00 * (v0.x + Dlt[nn][0]), e00,
                           e01 * (v0.y + Dlt[nn][1]), e01);
            if (ok1)
                red_add_v4(g_acc + (size_t)d1 * 128 + cb * 2,
                           e10 * (v1.x + Dlt[nn][2]), e10,
                           e11 * (v1.y + Dlt[nn][3]), e11);
        }
    }
}

// ---------------------------------------------------------------------------
// Output kernel (tensorized): out = relu((num/(den+1e-16)) @ W_out + b_out)
// ---------------------------------------------------------------------------
#define OUT_SMEM (4096 * 4 + 64 * 4)
__global__ void __launch_bounds__(256, 2) k_out(
        int N, const float* __restrict__ W_out, const float* __restrict__ b_out,
        float* __restrict__ out) {
    extern __shared__ unsigned smu[];
    unsigned* sW = smu;
    float* sB = (float*)(smu + 4096);

    prep_weights(W_out, sW, blockDim.x, threadIdx.x);
    if (threadIdx.x < 64) sB[threadIdx.x] = b_out[threadIdx.x];
    __syncthreads();

    const int lane = threadIdx.x & 31, warp = threadIdx.x >> 5;
    const int r0 = lane >> 2, m = lane & 3;
    const int gw = blockIdx.x * (blockDim.x >> 5) + warp;
    const int nw = gridDim.x * (blockDim.x >> 5);
    const int ntiles = (N + 15) >> 4;

    unsigned Ah[4][4], Al[4][4];
    float D[8][4];

    for (int t = gw; t < ntiles; t += nw) {
        const int base = t << 4;
        const int row0 = base + r0, row1 = base + r0 + 8;
        const bool ok0 = row0 < N, ok1 = row1 < N;
        const int rr0 = ok0 ? row0 : N - 1;
        const int rr1 = ok1 ? row1 : N - 1;

        #pragma unroll
        for (int kk = 0; kk < 4; kk++) {
            const int cb = kk * 16 + 2 * m;
            float4 a0 = *(const float4*)(g_acc + (size_t)rr0 * 128 + cb * 2);
            float4 a1 = *(const float4*)(g_acc + (size_t)rr1 * 128 + cb * 2);
            float4 a2 = *(const float4*)(g_acc + (size_t)rr0 * 128 + (cb + 8) * 2);
            float4 a3 = *(const float4*)(g_acc + (size_t)rr1 * 128 + (cb + 8) * 2);
            split_pair(__fdividef(a0.x, a0.y + 1e-16f), __fdividef(a0.z, a0.w + 1e-16f),
                       Ah[kk][0], Al[kk][0]);
            split_pair(__fdividef(a1.x, a1.y + 1e-16f), __fdividef(a1.z, a1.w + 1e-16f),
                       Ah[kk][1], Al[kk][1]);
            split_pair(__fdividef(a2.x, a2.y + 1e-16f), __fdividef(a2.z, a2.w + 1e-16f),
                       Ah[kk][2], Al[kk][2]);
            split_pair(__fdividef(a3.x, a3.y + 1e-16f), __fdividef(a3.z, a3.w + 1e-16f),
                       Ah[kk][3], Al[kk][3]);
        }

        gemm16<true>(D, Ah, Al, sW, sB, lane);

        #pragma unroll
        for (int nn = 0; nn < 8; nn++) {
            const int c = nn * 8 + 2 * m;
            if (ok0) *(float2*)(out + (size_t)row0 * 64 + c) =
                make_float2(fmaxf(D[nn][0], 0.f), fmaxf(D[nn][1], 0.f));
            if (ok1) *(float2*)(out + (size_t)row1 * 64 + c) =
                make_float2(fmaxf(D[nn][2], 0.f), fmaxf(D[nn][3], 0.f));
        }
    }
}

// ---------------------------------------------------------------------------

extern "C" void kernel_launch(void* const* d_in, const int* in_sizes, int n_in,
                              void* d_out, int out_size) {
    const float* x     = (const float*)d_in[0];
    const float* pos   = (const float*)d_in[1];
    const int*   ei    = (const int*)d_in[2];
    const float* W_in  = (const float*)d_in[3];
    const float* b_in  = (const float*)d_in[4];
    const float* ln_g  = (const float*)d_in[5];
    const float* ln_b  = (const float*)d_in[6];
    const float* W_lin = (const float*)d_in[7];
    const float* W_src = (const float*)d_in[8];
    const float* W_dst = (const float*)d_in[9];
    const float* pnW1  = (const float*)d_in[10];
    const float* pnb1  = (const float*)d_in[11];
    const float* pnW2  = (const float*)d_in[12];
    const float* pnb2  = (const float*)d_in[13];
    const float* anW1  = (const float*)d_in[14];
    const float* anb1  = (const float*)d_in[15];
    const float* anW2  = (const float*)d_in[16];
    const float* anb2  = (const float*)d_in[17];
    const float* W_out = (const float*)d_in[18];
    const float* b_out = (const float*)d_in[19];

    const int N = in_sizes[0] / 64;
    const int E = in_sizes[2] / 2;

    cudaFuncSetAttribute(k_node, cudaFuncAttributeMaxDynamicSharedMemorySize, NODE_SMEM);
    cudaFuncSetAttribute(k_edge, cudaFuncAttributeMaxDynamicSharedMemorySize, EDGE_SMEM);
    cudaFuncSetAttribute(k_out,  cudaFuncAttributeMaxDynamicSharedMemorySize, OUT_SMEM);

    const int ntiles = (E + 15) >> 4;
    const int mid = ntiles / 2;

    k_node<<<224, 256, NODE_SMEM>>>(N, x, W_in, b_in, ln_g, ln_b, W_lin, W_src, W_dst);
    k_edge<<<592, 128, EDGE_SMEM>>>(E, 0, mid, ei, pos, pnW1, pnb1, pnW2, pnb2,
                                    anW1, anb1, anW2, anb2);
    k_edge<<<592, 128, EDGE_SMEM>>>(E, mid, ntiles, ei, pos, pnW1, pnb1, pnW2, pnb2,
                                    anW1, anb1, anW2, anb2);
    k_out<<<224, 256, OUT_SMEM>>>(N, W_out, b_out, (float*)d_out);
}

// round 5
// speedup vs baseline: 3.8559x; 1.3329x over previous
#include <cuda_runtime.h>
#include <cuda_bf16.h>

#define CDIM 64
#define MAXN 100000

__device__ float g_q[MAXN * CDIM];
__device__ float g_k[MAXN * CDIM];
__device__ float g_v[MAXN * CDIM];
__device__ float g_acc[MAXN * CDIM * 2];   // [node][chan][{num, denom}]

__device__ __forceinline__ void red_add_v4(float* p, float a, float b, float c, float d) {
    asm volatile("red.global.add.v4.f32 [%0], {%1, %2, %3, %4};"
                 :: "l"(p), "f"(a), "f"(b), "f"(c), "f"(d) : "memory");
}
// pack two f32 into bf16x2: low 16 bits = lo_val, high = hi_val
__device__ __forceinline__ unsigned pack_bf16x2(float lo_val, float hi_val) {
    unsigned r;
    asm("cvt.rn.bf16x2.f32 %0, %1, %2;" : "=r"(r) : "f"(hi_val), "f"(lo_val));
    return r;
}
__device__ __forceinline__ float bfx2_lo_f32(unsigned p) { return __uint_as_float(p << 16); }
__device__ __forceinline__ float bfx2_hi_f32(unsigned p) { return __uint_as_float(p & 0xFFFF0000u); }

// split (v0,v1) into hi/lo bf16x2 pairs: v ~= hi + lo with ~2^-17 residual
__device__ __forceinline__ void split_pair(float v0, float v1, unsigned& hi, unsigned& lo) {
    hi = pack_bf16x2(v0, v1);
    float r0 = v0 - bfx2_lo_f32(hi);
    float r1 = v1 - bfx2_hi_f32(hi);
    lo = pack_bf16x2(r0, r1);
}

__device__ __forceinline__ void mma_bf16(float d[4],
        unsigned a0, unsigned a1, unsigned a2, unsigned a3,
        unsigned b0, unsigned b1) {
    asm("mma.sync.aligned.m16n8k16.row.col.f32.bf16.bf16.f32 "
        "{%0,%1,%2,%3}, {%4,%5,%6,%7}, {%8,%9}, {%0,%1,%2,%3};"
        : "+f"(d[0]), "+f"(d[1]), "+f"(d[2]), "+f"(d[3])
        : "r"(a0), "r"(a1), "r"(a2), "r"(a3), "r"(b0), "r"(b1));
}

// fp32 (64x64) weight matrix -> hi/lo bf16 B-fragments in smem
__device__ __forceinline__ void prep_weights(const float* __restrict__ W,
                                             unsigned* __restrict__ dstW,
                                             int tcount, int tid) {
    for (int i = tid; i < 4096; i += tcount) {
        int h = i >> 6, c = i & 63;
        float w = W[i];
        unsigned short hb = __bfloat16_as_ushort(__float2bfloat16(w));
        float hif = __uint_as_float((unsigned)hb << 16);
        unsigned short lb = __bfloat16_as_ushort(__float2bfloat16(w - hif));
        int kk = h >> 4, hh = h & 15;
        int e = hh & 1, mm = (hh >> 1) & 3, rg = hh >> 3;
        int nn = c >> 3, q = c & 7, ln = q * 4 + mm;
        unsigned short* p16 = (unsigned short*)(dstW + ((nn * 4 + kk) * 32 + ln) * 4);
        p16[rg * 2 + e]     = hb;
        p16[4 + rg * 2 + e] = lb;
    }
}

// 16xCx64 GEMM tile: 3-mma bf16 split per (nn,kk). D layout:
// D[nn][0]=(r0,8nn+2m) [1]=(r0,+1) [2]=(r1,8nn+2m) [3]=(r1,+1)
template<bool BIAS>
__device__ __forceinline__ void gemm16(float D[8][4],
        const unsigned Ah[4][4], const unsigned Al[4][4],
        const unsigned* __restrict__ sW, const float* __restrict__ bias, int lane) {
    const int m = lane & 3;
    #pragma unroll
    for (int nn = 0; nn < 8; nn++) {
        if (BIAS) {
            float2 b = *(const float2*)(bias + nn * 8 + 2 * m);
            D[nn][0] = b.x; D[nn][1] = b.y; D[nn][2] = b.x; D[nn][3] = b.y;
        } else {
            D[nn][0] = 0.f; D[nn][1] = 0.f; D[nn][2] = 0.f; D[nn][3] = 0.f;
        }
        #pragma unroll
        for (int kk = 0; kk < 4; kk++) {
            uint4 B = *(const uint4*)(sW + ((nn * 4 + kk) * 32 + lane) * 4);
            mma_bf16(D[nn], Ah[kk][0], Ah[kk][1], Ah[kk][2], Ah[kk][3], B.x, B.y);
            mma_bf16(D[nn], Al[kk][0], Al[kk][1], Al[kk][2], Al[kk][3], B.x, B.y);
            mma_bf16(D[nn], Ah[kk][0], Ah[kk][1], Ah[kk][2], Ah[kk][3], B.z, B.w);
        }
    }
}

// ---------------------------------------------------------------------------
// Node kernel (tensorized): 16 nodes per warp tile.
// H = LN(relu(X@W_in+b)); q=H@W_dst; k=H@W_src; v=H@W_lin. Also zeros g_acc.
// ---------------------------------------------------------------------------
#define NODE_SMEM (4 * 4096 * 4 + 192 * 4)
__global__ void __launch_bounds__(256, 2) k_node(
        int N, const float* __restrict__ x,
        const float* __restrict__ W_in, const float* __restrict__ b_in,
        const float* __restrict__ ln_g, const float* __restrict__ ln_b,
        const float* __restrict__ W_lin, const float* __restrict__ W_src,
        const float* __restrict__ W_dst) {
    extern __shared__ unsigned smu[];
    unsigned* sW = smu;                        // [W_in | Wq | Wk | Wv]
    float* sP = (float*)(smu + 16384);         // b_in[64], ln_g[64], ln_b[64]

    prep_weights(W_in,  sW,         blockDim.x, threadIdx.x);
    prep_weights(W_dst, sW + 4096,  blockDim.x, threadIdx.x);
    prep_weights(W_src, sW + 8192,  blockDim.x, threadIdx.x);
    prep_weights(W_lin, sW + 12288, blockDim.x, threadIdx.x);
    if (threadIdx.x < 64) {
        sP[threadIdx.x]       = b_in[threadIdx.x];
        sP[64 + threadIdx.x]  = ln_g[threadIdx.x];
        sP[128 + threadIdx.x] = ln_b[threadIdx.x];
    }
    __syncthreads();

    const int lane = threadIdx.x & 31, warp = threadIdx.x >> 5;
    const int r0 = lane >> 2, m = lane & 3;
    const int gw = blockIdx.x * (blockDim.x >> 5) + warp;
    const int nw = gridDim.x * (blockDim.x >> 5);
    const int ntiles = (N + 15) >> 4;

    unsigned Ah[4][4], Al[4][4];
    float D[8][4];

    for (int t = gw; t < ntiles; t += nw) {
        const int base = t << 4;
        const int row0 = base + r0, row1 = base + r0 + 8;
        const bool ok0 = row0 < N, ok1 = row1 < N;
        const int rr0 = ok0 ? row0 : N - 1;
        const int rr1 = ok1 ? row1 : N - 1;

        // gather X fragments
        #pragma unroll
        for (int kk = 0; kk < 4; kk++) {
            const int cb = kk * 16 + 2 * m;
            float2 xa = *(const float2*)(x + (size_t)rr0 * 64 + cb);
            float2 xb = *(const float2*)(x + (size_t)rr1 * 64 + cb);
            float2 xc = *(const float2*)(x + (size_t)rr0 * 64 + cb + 8);
            float2 xd = *(const float2*)(x + (size_t)rr1 * 64 + cb + 8);
            split_pair(xa.x, xa.y, Ah[kk][0], Al[kk][0]);
            split_pair(xb.x, xb.y, Ah[kk][1], Al[kk][1]);
            split_pair(xc.x, xc.y, Ah[kk][2], Al[kk][2]);
            split_pair(xd.x, xd.y, Ah[kk][3], Al[kk][3]);
        }

        // H = relu(X@W_in + b_in)
        gemm16<true>(D, Ah, Al, sW, sP, lane);
        #pragma unroll
        for (int nn = 0; nn < 8; nn++) {
            D[nn][0] = fmaxf(D[nn][0], 0.f); D[nn][1] = fmaxf(D[nn][1], 0.f);
            D[nn][2] = fmaxf(D[nn][2], 0.f); D[nn][3] = fmaxf(D[nn][3], 0.f);
        }

        // LayerNorm: row stats via quad (m-group) reduction
        float s0 = 0.f, q0 = 0.f, s1 = 0.f, q1 = 0.f;
        #pragma unroll
        for (int nn = 0; nn < 8; nn++) {
            s0 += D[nn][0] + D[nn][1];
            q0 += D[nn][0] * D[nn][0] + D[nn][1] * D[nn][1];
            s1 += D[nn][2] + D[nn][3];
            q1 += D[nn][2] * D[nn][2] + D[nn][3] * D[nn][3];
        }
        #pragma unroll
        for (int off = 1; off <= 2; off <<= 1) {
            s0 += __shfl_xor_sync(0xffffffffu, s0, off);
            q0 += __shfl_xor_sync(0xffffffffu, q0, off);
            s1 += __shfl_xor_sync(0xffffffffu, s1, off);
            q1 += __shfl_xor_sync(0xffffffffu, q1, off);
        }
        float mu0 = s0 * 0.015625f, mu1 = s1 * 0.015625f;
        float inv0 = rsqrtf(q0 * 0.015625f - mu0 * mu0 + 1e-5f);
        float inv1 = rsqrtf(q1 * 0.015625f - mu1 * mu1 + 1e-5f);

        // normalize + handoff into A fragments (D-layout == A-layout)
        #pragma unroll
        for (int kk = 0; kk < 4; kk++) {
            const int c = kk * 16 + 2 * m;
            float2 ga = *(const float2*)(sP + 64 + c);
            float2 ba = *(const float2*)(sP + 128 + c);
            float2 gb = *(const float2*)(sP + 64 + c + 8);
            float2 bb = *(const float2*)(sP + 128 + c + 8);
            float h00 = (D[2*kk][0]   - mu0) * inv0 * ga.x + ba.x;
            float h01 = (D[2*kk][1]   - mu0) * inv0 * ga.y + ba.y;
            float h10 = (D[2*kk][2]   - mu1) * inv1 * ga.x + ba.x;
            float h11 = (D[2*kk][3]   - mu1) * inv1 * ga.y + ba.y;
            float h08 = (D[2*kk+1][0] - mu0) * inv0 * gb.x + bb.x;
            float h09 = (D[2*kk+1][1] - mu0) * inv0 * gb.y + bb.y;
            float h18 = (D[2*kk+1][2] - mu1) * inv1 * gb.x + bb.x;
            float h19 = (D[2*kk+1][3] - mu1) * inv1 * gb.y + bb.y;
            split_pair(h00, h01, Ah[kk][0], Al[kk][0]);
            split_pair(h10, h11, Ah[kk][1], Al[kk][1]);
            split_pair(h08, h09, Ah[kk][2], Al[kk][2]);
            split_pair(h18, h19, Ah[kk][3], Al[kk][3]);
        }

        // q / k / v GEMMs + stores
        gemm16<false>(D, Ah, Al, sW + 4096, nullptr, lane);
        #pragma unroll
        for (int nn = 0; nn < 8; nn++) {
            const int c = nn * 8 + 2 * m;
            if (ok0) *(float2*)(g_q + (size_t)row0 * 64 + c) = make_float2(D[nn][0], D[nn][1]);
            if (ok1) *(float2*)(g_q + (size_t)row1 * 64 + c) = make_float2(D[nn][2], D[nn][3]);
        }
        gemm16<false>(D, Ah, Al, sW + 8192, nullptr, lane);
        #pragma unroll
        for (int nn = 0; nn < 8; nn++) {
            const int c = nn * 8 + 2 * m;
            if (ok0) *(float2*)(g_k + (size_t)row0 * 64 + c) = make_float2(D[nn][0], D[nn][1]);
            if (ok1) *(float2*)(g_k + (size_t)row1 * 64 + c) = make_float2(D[nn][2], D[nn][3]);
        }
        gemm16<false>(D, Ah, Al, sW + 12288, nullptr, lane);
        #pragma unroll
        for (int nn = 0; nn < 8; nn++) {
            const int c = nn * 8 + 2 * m;
            if (ok0) *(float2*)(g_v + (size_t)row0 * 64 + c) = make_float2(D[nn][0], D[nn][1]);
            if (ok1) *(float2*)(g_v + (size_t)row1 * 64 + c) = make_float2(D[nn][2], D[nn][3]);
        }

        // zero g_acc for these 16 nodes (512 float4)
        float4* accz = (float4*)(g_acc + (size_t)base * 128);
        #pragma unroll
        for (int i = 0; i < 16; i++) {
            int idx = i * 32 + lane;
            if (base + (idx >> 5) < N)
                accz[idx] = make_float4(0.f, 0.f, 0.f, 0.f);
        }
    }
}

// ---------------------------------------------------------------------------
// Edge kernel: 16-edge tiles on mma.sync. Gathers hoisted ahead of the mma
// chains (q-k before GEMM1, v before GEMM3) to overlap latency; occupancy cap
// relaxed to 3 blocks/SM (170 regs) to avoid local-memory spills.
// ---------------------------------------------------------------------------
#define EDGE_SMEM (3 * 4096 * 4 + 64 * 16 + 3 * 64 * 4)   // 50944 B

__global__ void __launch_bounds__(128, 3) k_edge(
        int E,
        const int* __restrict__ ei, const float* __restrict__ pos,
        const float* __restrict__ pnW1, const float* __restrict__ pnb1,
        const float* __restrict__ pnW2, const float* __restrict__ pnb2,
        const float* __restrict__ anW1, const float* __restrict__ anb1,
        const float* __restrict__ anW2, const float* __restrict__ anb2) {
    extern __shared__ unsigned smu[];
    unsigned* sWL = smu;                          // 3 * 4096 u32
    float4*  sW1  = (float4*)(smu + 12288);       // {W1[0][c],W1[1][c],W1[2][c],b1[c]}
    float*   sB   = (float*)(smu + 12288 + 256);  // pnb2 | anb1 | anb2

    prep_weights(pnW2, sWL,        128, threadIdx.x);
    prep_weights(anW1, sWL + 4096, 128, threadIdx.x);
    prep_weights(anW2, sWL + 8192, 128, threadIdx.x);
    if (threadIdx.x < 64) {
        int c = threadIdx.x;
        sW1[c] = make_float4(pnW1[c], pnW1[64 + c], pnW1[128 + c], pnb1[c]);
        sB[c]        = pnb2[c];
        sB[64 + c]   = anb1[c];
        sB[128 + c]  = anb2[c];
    }
    __syncthreads();

    const int lane = threadIdx.x & 31, warp = threadIdx.x >> 5;
    const int r0 = lane >> 2, m = lane & 3;
    const int gw = blockIdx.x * 4 + warp;
    const int nw = gridDim.x * 4;
    const int ntiles = (E + 15) >> 4;

    unsigned Ah[4][4], Al[4][4];
    float D[8][4];
    float Dlt[8][4];   // delta, then reused pattern below
    float QK[8][4];    // q[d]-k[s] preloaded (same index layout as Dlt)

    for (int t = gw; t < ntiles; t += nw) {
        const int base = t << 4;
        const int er0 = base + r0, er1 = base + r0 + 8;
        const bool ok0 = er0 < E, ok1 = er1 < E;
        const int ec0 = ok0 ? er0 : E - 1;
        const int ec1 = ok1 ? er1 : E - 1;
        const int s0 = ei[ec0],     s1 = ei[ec1];
        const int d0 = ei[E + ec0], d1 = ei[E + ec1];

        const float p00 = pos[d0 * 3 + 0] - pos[s0 * 3 + 0];
        const float p01 = pos[d0 * 3 + 1] - pos[s0 * 3 + 1];
        const float p02 = pos[d0 * 3 + 2] - pos[s0 * 3 + 2];
        const float p10 = pos[d1 * 3 + 0] - pos[s1 * 3 + 0];
        const float p11 = pos[d1 * 3 + 1] - pos[s1 * 3 + 1];
        const float p12 = pos[d1 * 3 + 2] - pos[s1 * 3 + 2];

        // hoist q/k gathers: independent of GEMM1, overlap their latency
        #pragma unroll
        for (int kk = 0; kk < 4; kk++) {
            const int cb = kk * 16 + 2 * m;
            float2 qa = *(const float2*)(g_q + (size_t)d0 * 64 + cb);
            float2 ka = *(const float2*)(g_k + (size_t)s0 * 64 + cb);
            float2 qb = *(const float2*)(g_q + (size_t)d1 * 64 + cb);
            float2 kb = *(const float2*)(g_k + (size_t)s1 * 64 + cb);
            float2 qc = *(const float2*)(g_q + (size_t)d0 * 64 + cb + 8);
            float2 kc = *(const float2*)(g_k + (size_t)s0 * 64 + cb + 8);
            float2 qd = *(const float2*)(g_q + (size_t)d1 * 64 + cb + 8);
            float2 kd = *(const float2*)(g_k + (size_t)s1 * 64 + cb + 8);
            QK[2*kk][0]   = qa.x - ka.x; QK[2*kk][1]   = qa.y - ka.y;
            QK[2*kk][2]   = qb.x - kb.x; QK[2*kk][3]   = qb.y - kb.y;
            QK[2*kk+1][0] = qc.x - kc.x; QK[2*kk+1][1] = qc.y - kc.y;
            QK[2*kk+1][2] = qd.x - kd.x; QK[2*kk+1][3] = qd.y - kd.y;
        }

        // pos MLP layer 1 (3 -> 64), fp32, direct into A fragments
        #pragma unroll
        for (int kk = 0; kk < 4; kk++) {
            const int cb = kk * 16 + 2 * m;
            float4 wA = sW1[cb],     wB = sW1[cb + 1];
            float4 wC = sW1[cb + 8], wD = sW1[cb + 9];
            float h00 = fmaxf(fmaf(p02, wA.z, fmaf(p01, wA.y, fmaf(p00, wA.x, wA.w))), 0.f);
            float h01 = fmaxf(fmaf(p02, wB.z, fmaf(p01, wB.y, fmaf(p00, wB.x, wB.w))), 0.f);
            float h10 = fmaxf(fmaf(p12, wA.z, fmaf(p11, wA.y, fmaf(p10, wA.x, wA.w))), 0.f);
            float h11 = fmaxf(fmaf(p12, wB.z, fmaf(p11, wB.y, fmaf(p10, wB.x, wB.w))), 0.f);
            float h08 = fmaxf(fmaf(p02, wC.z, fmaf(p01, wC.y, fmaf(p00, wC.x, wC.w))), 0.f);
            float h09 = fmaxf(fmaf(p02, wD.z, fmaf(p01, wD.y, fmaf(p00, wD.x, wD.w))), 0.f);
            float h18 = fmaxf(fmaf(p12, wC.z, fmaf(p11, wC.y, fmaf(p10, wC.x, wC.w))), 0.f);
            float h19 = fmaxf(fmaf(p12, wD.z, fmaf(p11, wD.y, fmaf(p10, wD.x, wD.w))), 0.f);
            split_pair(h00, h01, Ah[kk][0], Al[kk][0]);
            split_pair(h10, h11, Ah[kk][1], Al[kk][1]);
            split_pair(h08, h09, Ah[kk][2], Al[kk][2]);
            split_pair(h18, h19, Ah[kk][3], Al[kk][3]);
        }

        // GEMM1: delta = relu(H1 @ pnW2 + pnb2)
        gemm16<true>(D, Ah, Al, sWL, sB, lane);
        #pragma unroll
        for (int nn = 0; nn < 8; nn++) {
            Dlt[nn][0] = fmaxf(D[nn][0], 0.f);
            Dlt[nn][1] = fmaxf(D[nn][1], 0.f);
            Dlt[nn][2] = fmaxf(D[nn][2], 0.f);
            Dlt[nn][3] = fmaxf(D[nn][3], 0.f);
        }

        // A2 = (q[d] - k[s]) + delta  (gathers already in QK)
        #pragma unroll
        for (int kk = 0; kk < 4; kk++) {
            split_pair(QK[2*kk][0]   + Dlt[2*kk][0],   QK[2*kk][1]   + Dlt[2*kk][1],   Ah[kk][0], Al[kk][0]);
            split_pair(QK[2*kk][2]   + Dlt[2*kk][2],   QK[2*kk][3]   + Dlt[2*kk][3],   Ah[kk][1], Al[kk][1]);
            split_pair(QK[2*kk+1][0] + Dlt[2*kk+1][0], QK[2*kk+1][1] + Dlt[2*kk+1][1], Ah[kk][2], Al[kk][2]);
            split_pair(QK[2*kk+1][2] + Dlt[2*kk+1][2], QK[2*kk+1][3] + Dlt[2*kk+1][3], Ah[kk][3], Al[kk][3]);
        }

        // GEMM2: G = relu(A2 @ anW1 + anb1)
        gemm16<true>(D, Ah, Al, sWL + 4096, sB + 64, lane);
        #pragma unroll
        for (int kk = 0; kk < 4; kk++) {
            split_pair(fmaxf(D[2*kk][0], 0.f),   fmaxf(D[2*kk][1], 0.f),   Ah[kk][0], Al[kk][0]);
            split_pair(fmaxf(D[2*kk][2], 0.f),   fmaxf(D[2*kk][3], 0.f),   Ah[kk][1], Al[kk][1]);
            split_pair(fmaxf(D[2*kk+1][0], 0.f), fmaxf(D[2*kk+1][1], 0.f), Ah[kk][2], Al[kk][2]);
            split_pair(fmaxf(D[2*kk+1][2], 0.f), fmaxf(D[2*kk+1][3], 0.f), Ah[kk][3], Al[kk][3]);
        }

        // hoist v gathers: independent of GEMM3 (reuse QK storage)
        #pragma unroll
        for (int nn = 0; nn < 8; nn++) {
            const int cb = nn * 8 + 2 * m;
            float2 v0 = *(const float2*)(g_v + (size_t)s0 * 64 + cb);
            float2 v1 = *(const float2*)(g_v + (size_t)s1 * 64 + cb);
            QK[nn][0] = v0.x; QK[nn][1] = v0.y;
            QK[nn][2] = v1.x; QK[nn][3] = v1.y;
        }

        // GEMM3: alpha = G @ anW2 + anb2
        gemm16<true>(D, Ah, Al, sWL + 8192, sB + 128, lane);

        // epilogue: e = exp(relu(alpha)); RED {e*(v+delta), e}
        #pragma unroll
        for (int nn = 0; nn < 8; nn++) {
            const int cb = nn * 8 + 2 * m;
            float e00 = __expf(fmaxf(D[nn][0], 0.f));
            float e01 = __expf(fmaxf(D[nn][1], 0.f));
            float e10 = __expf(fmaxf(D[nn][2], 0.f));
            float e11 = __expf(fmaxf(D[nn][3], 0.f));
            if (ok0)
                red_add_v4(g_acc + (size_t)d0 * 128 + cb * 2,
                           e00 * (QK[nn][0] + Dlt[nn][0]), e00,
                           e01 * (QK[nn][1] + Dlt[nn][1]), e01);
            if (ok1)
                red_add_v4(g_acc + (size_t)d1 * 128 + cb * 2,
                           e10 * (QK[nn][2] + Dlt[nn][2]), e10,
                           e11 * (QK[nn][3] + Dlt[nn][3]), e11);
        }
    }
}

// ---------------------------------------------------------------------------
// Output kernel (tensorized): out = relu((num/(den+1e-16)) @ W_out + b_out)
// ---------------------------------------------------------------------------
#define OUT_SMEM (4096 * 4 + 64 * 4)
__global__ void __launch_bounds__(256, 2) k_out(
        int N, const float* __restrict__ W_out, const float* __restrict__ b_out,
        float* __restrict__ out) {
    extern __shared__ unsigned smu[];
    unsigned* sW = smu;
    float* sB = (float*)(smu + 4096);

    prep_weights(W_out, sW, blockDim.x, threadIdx.x);
    if (threadIdx.x < 64) sB[threadIdx.x] = b_out[threadIdx.x];
    __syncthreads();

    const int lane = threadIdx.x & 31, warp = threadIdx.x >> 5;
    const int r0 = lane >> 2, m = lane & 3;
    const int gw = blockIdx.x * (blockDim.x >> 5) + warp;
    const int nw = gridDim.x * (blockDim.x >> 5);
    const int ntiles = (N + 15) >> 4;

    unsigned Ah[4][4], Al[4][4];
    float D[8][4];

    for (int t = gw; t < ntiles; t += nw) {
        const int base = t << 4;
        const int row0 = base + r0, row1 = base + r0 + 8;
        const bool ok0 = row0 < N, ok1 = row1 < N;
        const int rr0 = ok0 ? row0 : N - 1;
        const int rr1 = ok1 ? row1 : N - 1;

        #pragma unroll
        for (int kk = 0; kk < 4; kk++) {
            const int cb = kk * 16 + 2 * m;
            float4 a0 = *(const float4*)(g_acc + (size_t)rr0 * 128 + cb * 2);
            float4 a1 = *(const float4*)(g_acc + (size_t)rr1 * 128 + cb * 2);
            float4 a2 = *(const float4*)(g_acc + (size_t)rr0 * 128 + (cb + 8) * 2);
            float4 a3 = *(const float4*)(g_acc + (size_t)rr1 * 128 + (cb + 8) * 2);
            split_pair(__fdividef(a0.x, a0.y + 1e-16f), __fdividef(a0.z, a0.w + 1e-16f),
                       Ah[kk][0], Al[kk][0]);
            split_pair(__fdividef(a1.x, a1.y + 1e-16f), __fdividef(a1.z, a1.w + 1e-16f),
                       Ah[kk][1], Al[kk][1]);
            split_pair(__fdividef(a2.x, a2.y + 1e-16f), __fdividef(a2.z, a2.w + 1e-16f),
                       Ah[kk][2], Al[kk][2]);
            split_pair(__fdividef(a3.x, a3.y + 1e-16f), __fdividef(a3.z, a3.w + 1e-16f),
                       Ah[kk][3], Al[kk][3]);
        }

        gemm16<true>(D, Ah, Al, sW, sB, lane);

        #pragma unroll
        for (int nn = 0; nn < 8; nn++) {
            const int c = nn * 8 + 2 * m;
            if (ok0) *(float2*)(out + (size_t)row0 * 64 + c) =
                make_float2(fmaxf(D[nn][0], 0.f), fmaxf(D[nn][1], 0.f));
            if (ok1) *(float2*)(out + (size_t)row1 * 64 + c) =
                make_float2(fmaxf(D[nn][2], 0.f), fmaxf(D[nn][3], 0.f));
        }
    }
}

// ---------------------------------------------------------------------------

extern "C" void kernel_launch(void* const* d_in, const int* in_sizes, int n_in,
                              void* d_out, int out_size) {
    const float* x     = (const float*)d_in[0];
    const float* pos   = (const float*)d_in[1];
    const int*   ei    = (const int*)d_in[2];
    const float* W_in  = (const float*)d_in[3];
    const float* b_in  = (const float*)d_in[4];
    const float* ln_g  = (const float*)d_in[5];
    const float* ln_b  = (const float*)d_in[6];
    const float* W_lin = (const float*)d_in[7];
    const float* W_src = (const float*)d_in[8];
    const float* W_dst = (const float*)d_in[9];
    const float* pnW1  = (const float*)d_in[10];
    const float* pnb1  = (const float*)d_in[11];
    const float* pnW2  = (const float*)d_in[12];
    const float* pnb2  = (const float*)d_in[13];
    const float* anW1  = (const float*)d_in[14];
    const float* anb1  = (const float*)d_in[15];
    const float* anW2  = (const float*)d_in[16];
    const float* anb2  = (const float*)d_in[17];
    const float* W_out = (const float*)d_in[18];
    const float* b_out = (const float*)d_in[19];

    const int N = in_sizes[0] / 64;
    const int E = in_sizes[2] / 2;

    cudaFuncSetAttribute(k_node, cudaFuncAttributeMaxDynamicSharedMemorySize, NODE_SMEM);
    cudaFuncSetAttribute(k_edge, cudaFuncAttributeMaxDynamicSharedMemorySize, EDGE_SMEM);
    cudaFuncSetAttribute(k_out,  cudaFuncAttributeMaxDynamicSharedMemorySize, OUT_SMEM);

    k_node<<<224, 256, NODE_SMEM>>>(N, x, W_in, b_in, ln_g, ln_b, W_lin, W_src, W_dst);
    k_edge<<<444, 128, EDGE_SMEM>>>(E, ei, pos, pnW1, pnb1, pnW2, pnb2,
                                    anW1, anb1, anW2, anb2);
    k_out<<<224, 256, OUT_SMEM>>>(N, W_out, b_out, (float*)d_out);
}